// round 3
// baseline (speedup 1.0000x reference)
#include <cuda_runtime.h>
#include <cstdint>

#define NPTS   16384
#define NB     4
#define MPER   4096
#define NCENT  (NB*MPER)          // 16384 centroids
#define KNBR   33                 // K+1
#define NEDGE  (NCENT*KNBR)       // 540672 edges
#define H1DIM  128
#define H2DIM  256
#define CDIM   32
#define R2CONST 0.04f

#define OUT_POS_OFF   (NCENT*H2DIM)
#define OUT_BATCH_OFF (OUT_POS_OFF + NCENT*3)

typedef unsigned long long ull;

// -------------------- device scratch --------------------------------------
__device__ int   g_fps[NCENT];
__device__ int   g_gidx[NCENT];
__device__ float g_cent[NCENT*3];
__device__ int   g_nbr[NEDGE];
__device__ int   g_sorttmp[NB*NPTS];                // FPS cell-sorted order
__device__ float g_A  [(size_t)NB*NPTS*H1DIM];
__device__ float g_H1 [(size_t)NEDGE*H1DIM];
__device__ float g_H2 [(size_t)NEDGE*H2DIM];
__device__ float g_agg[(size_t)NCENT*H2DIM];

// -------------------- 1) bucketed farthest point sampling ------------------
// Exact-equivalent FPS: 8^3 grid, per-cell packed max keys, conservative AABB
// lower-bound pruning of updates. One CTA (512 threads) per cloud.
__device__ __forceinline__ int cellof(float x, float y, float z) {
    int ix = (int)(x * 8.0f); ix = ix < 0 ? 0 : (ix > 7 ? 7 : ix);
    int iy = (int)(y * 8.0f); iy = iy < 0 ? 0 : (iy > 7 ? 7 : iy);
    int iz = (int)(z * 8.0f); iz = iz < 0 ? 0 : (iz > 7 ? 7 : iz);
    return (iz << 6) | (iy << 3) | ix;
}

__global__ void __launch_bounds__(512,1) fps_kernel(const float* __restrict__ pos) {
    int b = blockIdx.x;
    extern __shared__ float sm[];
    float* Xs = sm; float* Ys = sm + NPTS; float* Zs = sm + 2*NPTS;
    __shared__ ull      cellkey[512];
    __shared__ int      cellcnt[512];
    __shared__ int      cellptr[512];
    __shared__ unsigned dirtybits[17];
    __shared__ ull      wred[16];
    __shared__ float    qsh[3];
    int tid = threadIdx.x, lane = tid & 31, wid = tid >> 5;
    const float* p = pos + (size_t)b*NPTS*3;

    for (int i = tid; i < NPTS; i += 512) {
        Xs[i] = p[3*i]; Ys[i] = p[3*i+1]; Zs[i] = p[3*i+2];
    }
    cellcnt[tid] = 0;
    cellkey[tid] = 0ull;
    if (tid == 0) dirtybits[16] = 0u;
    __syncthreads();

    // count points per cell
    for (int i = tid; i < NPTS; i += 512)
        atomicAdd(&cellcnt[cellof(Xs[i], Ys[i], Zs[i])], 1);
    __syncthreads();

    // exclusive prefix sum over 512 counts (warp 0)
    if (wid == 0) {
        int carry = 0;
        for (int cc = 0; cc < 16; cc++) {
            int v0 = cellcnt[cc*32 + lane];
            int v = v0;
#pragma unroll
            for (int off = 1; off < 32; off <<= 1) {
                int o = __shfl_up_sync(0xffffffffu, v, off);
                if (lane >= off) v += o;
            }
            int tot = __shfl_sync(0xffffffffu, v, 31);
            cellptr[cc*32 + lane] = v - v0 + carry;
            carry += tot;
        }
    }
    __syncthreads();

    // scatter original indices into cell-sorted order (via global temp)
    for (int i = tid; i < NPTS; i += 512) {
        int c = cellof(Xs[i], Ys[i], Zs[i]);
        int slot = atomicAdd(&cellptr[c], 1);
        g_sorttmp[b*NPTS + slot] = i;
    }
    __syncthreads();

    // per-thread ownership of 32 consecutive sorted slots
    float M[32];
    unsigned op[16];     // packed u16 original indices
    unsigned bp[8];      // packed u8 cell offsets relative to w0*32
    int c0 = 0, c1 = 0, w0 = 0;
    bool fallback = false;
#pragma unroll
    for (int k = 0; k < 8; k++) bp[k] = 0u;
#pragma unroll
    for (int k = 0; k < 16; k++) op[k] = 0u;
    {
        float q0x = Xs[0], q0y = Ys[0], q0z = Zs[0];
        int base = b*NPTS + tid*32;
#pragma unroll
        for (int k = 0; k < 32; k++) {
            int o = g_sorttmp[base + k];
            float x = Xs[o], y = Ys[o], z = Zs[o];
            int c = cellof(x, y, z);
            if (k == 0) { c0 = c; w0 = c >> 5; }
            c1 = c;
            int rel = c - (w0 << 5);
            if (rel >= 64) fallback = true;
            bp[k >> 2] |= (unsigned)(rel & 0xff) << ((k & 3) * 8);
            op[k >> 1] |= (unsigned)o << ((k & 1) * 16);
            float dx = x - q0x, dy = y - q0y, dz = z - q0z;
            float d2 = fmaf(dz, dz, fmaf(dy, dy, dx*dx));
            M[k] = d2;
            ull key = ((ull)__float_as_uint(d2) << 32) | (unsigned)(NPTS - 1 - o);
            atomicMax(&cellkey[c], key);
        }
    }
    if (tid == 0) g_fps[b*MPER] = 0;
    __syncthreads();

    const float CS = 0.125f;
    int myix = tid & 7, myiy = (tid >> 3) & 7, myiz = tid >> 6;
    float lox = myix * CS, loy = myiy * CS, loz = myiz * CS;
    float hix = lox + CS, hiy = loy + CS, hiz = loz + CS;

    for (int t = 1; t < MPER; t++) {
        // ---- argmax over 512 cell keys ----
        ull key = cellkey[tid];
        ull mykey = key;
#pragma unroll
        for (int off = 16; off > 0; off >>= 1) {
            ull o2 = __shfl_down_sync(0xffffffffu, key, off);
            if (o2 > key) key = o2;
        }
        if (lane == 0) wred[wid] = key;
        __syncthreads();
        if (wid == 0) {
            ull k2 = (lane < 16) ? wred[lane] : 0ull;
#pragma unroll
            for (int off = 8; off > 0; off >>= 1) {
                ull o2 = __shfl_down_sync(0xffffffffu, k2, off);
                if (o2 > k2) k2 = o2;
            }
            if (lane == 0) {
                int sel = NPTS - 1 - (int)(k2 & 0xffffffffu);
                g_fps[b*MPER + t] = sel;
                qsh[0] = Xs[sel]; qsh[1] = Ys[sel]; qsh[2] = Zs[sel];
            }
        }
        __syncthreads();
        float qx = qsh[0], qy = qsh[1], qz = qsh[2];

        // ---- dirty determination for cell 'tid' (AABB lower bound) ----
        float cm = __uint_as_float((unsigned)(mykey >> 32));
        float lbx = fmaxf(fmaxf(lox - qx, qx - hix), 0.0f);
        float lby = fmaxf(fmaxf(loy - qy, qy - hiy), 0.0f);
        float lbz = fmaxf(fmaxf(loz - qz, qz - hiz), 0.0f);
        float lb2 = fmaf(lbz, lbz, fmaf(lby, lby, lbx*lbx));
        bool d = lb2 < cm;
        unsigned msk = __ballot_sync(0xffffffffu, d);
        if (lane == 0) dirtybits[wid] = msk;
        if (d) cellkey[tid] = 0ull;
        __syncthreads();

        // ---- update points in dirty cells ----
        unsigned any = 0;
        {
            int w1 = c1 >> 5;
            int bA = c0 & 31, bB = c1 & 31;
            for (int w = w0; w <= w1; ++w) {
                unsigned m = dirtybits[w];
                if (w == w0) m &= (0xffffffffu << bA);
                if (w == w1) m &= (bB == 31) ? 0xffffffffu : ((1u << (bB + 1)) - 1u);
                any |= m;
            }
        }
        if (any) {
            if (!fallback) {
                ull dw = (ull)dirtybits[w0] | ((ull)dirtybits[w0 + 1] << 32);
#pragma unroll
                for (int k = 0; k < 32; k++) {
                    int rel = (bp[k >> 2] >> ((k & 3) * 8)) & 0xff;
                    if ((dw >> rel) & 1ull) {
                        int o = (op[k >> 1] >> ((k & 1) * 16)) & 0xffff;
                        float dx = Xs[o]-qx, dy = Ys[o]-qy, dz = Zs[o]-qz;
                        float d2 = fmaf(dz, dz, fmaf(dy, dy, dx*dx));
                        float nm = fminf(M[k], d2);
                        M[k] = nm;
                        ull nk = ((ull)__float_as_uint(nm) << 32) | (unsigned)(NPTS - 1 - o);
                        atomicMax(&cellkey[(w0 << 5) + rel], nk);
                    }
                }
            } else {
#pragma unroll
                for (int k = 0; k < 32; k++) {
                    int o = (op[k >> 1] >> ((k & 1) * 16)) & 0xffff;
                    float x = Xs[o], y = Ys[o], z = Zs[o];
                    int c = cellof(x, y, z);
                    if ((dirtybits[c >> 5] >> (c & 31)) & 1u) {
                        float dx = x-qx, dy = y-qy, dz = z-qz;
                        float d2 = fmaf(dz, dz, fmaf(dy, dy, dx*dx));
                        float nm = fminf(M[k], d2);
                        M[k] = nm;
                        ull nk = ((ull)__float_as_uint(nm) << 32) | (unsigned)(NPTS - 1 - o);
                        atomicMax(&cellkey[c], nk);
                    }
                }
            }
        }
        __syncthreads();
    }
}

// -------------------- 2) gather centroids + write pos/batch outputs --------
__global__ void gather_kernel(const float* __restrict__ pos,
                              const int* __restrict__ batch,
                              float* __restrict__ dout) {
    int i = blockIdx.x*blockDim.x + threadIdx.x;
    if (i >= NCENT) return;
    int b = i >> 12;
    int sel = g_fps[i];
    int g = b*NPTS + sel;
    float x = pos[3*g], y = pos[3*g+1], z = pos[3*g+2];
    g_cent[3*i] = x; g_cent[3*i+1] = y; g_cent[3*i+2] = z;
    g_gidx[i] = g;
    dout[OUT_POS_OFF + 3*i]   = x;
    dout[OUT_POS_OFF + 3*i+1] = y;
    dout[OUT_POS_OFF + 3*i+2] = z;
    dout[OUT_BATCH_OFF + i]   = (float)batch[g];
}

// -------------------- 3) ball query: 33 nearest within r -------------------
#define BQ_TILE 2048
#define BQ_CAP  1024
__global__ void __launch_bounds__(256,1) ballquery_kernel(const float* __restrict__ pos) {
    extern __shared__ float sm[];
    float* Xs = sm; float* Ys = sm + BQ_TILE; float* Zs = sm + 2*BQ_TILE;
    ull* buf = (ull*)(sm + 3*BQ_TILE);
    int tid = threadIdx.x;
    int wid = tid >> 5, lane = tid & 31;
    int c = blockIdx.x*8 + wid;
    int cloud = c >> 12;
    const float* pcloud = pos + (size_t)cloud*NPTS*3;
    float cx = g_cent[3*c], cy = g_cent[3*c+1], cz = g_cent[3*c+2];
    ull* mybuf = buf + (size_t)wid*BQ_CAP;
    int cnt = 0;
    for (int tile = 0; tile < NPTS/BQ_TILE; ++tile) {
        for (int i = tid; i < BQ_TILE; i += 256) {
            int pidx = tile*BQ_TILE + i;
            Xs[i] = pcloud[3*pidx]; Ys[i] = pcloud[3*pidx+1]; Zs[i] = pcloud[3*pidx+2];
        }
        __syncthreads();
        for (int i = lane; i < BQ_TILE; i += 32) {
            float dx = Xs[i]-cx, dy = Ys[i]-cy, dz = Zs[i]-cz;
            float d2 = fmaf(dz,dz,fmaf(dy,dy,dx*dx));
            bool hit = (d2 <= R2CONST);
            unsigned m = __ballot_sync(0xffffffffu, hit);
            int pre = __popc(m & ((1u << lane) - 1u));
            if (hit) {
                int slot = cnt + pre;
                if (slot < BQ_CAP)
                    mybuf[slot] = ((ull)__float_as_uint(d2) << 32)
                                | (unsigned)(tile*BQ_TILE + i);
            }
            cnt += __popc(m);
        }
        __syncthreads();
    }
    if (cnt > BQ_CAP) cnt = BQ_CAP;
    int selfg = g_gidx[c];
    for (int it = 0; it < KNBR; ++it) {
        ull mn = ~0ull;
        for (int j = lane; j < cnt; j += 32) {
            ull v = mybuf[j];
            if (v < mn) mn = v;
        }
#pragma unroll
        for (int off = 16; off > 0; off >>= 1) {
            ull o = __shfl_down_sync(0xffffffffu, mn, off);
            if (o < mn) mn = o;
        }
        mn = __shfl_sync(0xffffffffu, mn, 0);
        int nbr;
        if (mn == ~0ull) {
            nbr = selfg;
        } else {
            nbr = cloud*NPTS + (int)(mn & 0xffffffffu);
            for (int j = lane; j < cnt; j += 32)
                if (mybuf[j] == mn) mybuf[j] = ~0ull;
        }
        if (lane == 0) g_nbr[c*KNBR + it] = nbr;
    }
}

// -------------------- 4) per-point layer-1 x-part --------------------------
__global__ void pfeat_kernel(const float* __restrict__ x,
                             const float* __restrict__ lw1,
                             const float* __restrict__ lb1) {
    int idx = blockIdx.x*blockDim.x + threadIdx.x;
    int p = idx >> 7, ch = idx & 127;
    float acc = lb1[ch];
    const float* xp = x + (size_t)p*CDIM;
#pragma unroll
    for (int j = 0; j < CDIM; j++)
        acc = fmaf(xp[j], lw1[j*H1DIM + ch], acc);
    g_A[(size_t)p*H1DIM + ch] = acc;
}

// -------------------- 5) per-edge layer-1 ----------------------------------
__global__ void eh1_kernel(const float* __restrict__ pos,
                           const float* __restrict__ lw1) {
    int idx = blockIdx.x*blockDim.x + threadIdx.x;
    int e = idx >> 7, k = idx & 127;
    int c = e / KNBR;
    int col = g_nbr[e];
    float dx = pos[3*col]   - g_cent[3*c];
    float dy = pos[3*col+1] - g_cent[3*c+1];
    float dz = pos[3*col+2] - g_cent[3*c+2];
    float h = g_A[(size_t)col*H1DIM + k];
    h = fmaf(dx, lw1[32*H1DIM + k], h);
    h = fmaf(dy, lw1[33*H1DIM + k], h);
    h = fmaf(dz, lw1[34*H1DIM + k], h);
    g_H1[(size_t)e*H1DIM + k] = fmaxf(h, 0.0f);
}

// -------------------- 6) tiled SGEMM, C = relu(A@B + bias) -----------------
__global__ void __launch_bounds__(256) sgemm_kernel(const float* __restrict__ A,
                                                    const float* __restrict__ Bw,
                                                    const float* __restrict__ bias,
                                                    float* __restrict__ C,
                                                    int Kdim) {
    __shared__ float As[8][128];
    __shared__ float Bs[8][128];
    int t = threadIdx.x;
    int tx = t & 15, ty = t >> 4;
    int m0 = blockIdx.x * 128, n0 = blockIdx.y * 128;
    float acc[8][8];
#pragma unroll
    for (int i = 0; i < 8; i++)
#pragma unroll
        for (int j = 0; j < 8; j++) acc[i][j] = 0.f;
    int r  = t >> 1, cc4 = (t & 1) * 4;
    int r2 = t >> 5, c2  = (t & 31) * 4;
    for (int k0 = 0; k0 < Kdim; k0 += 8) {
        float4 av = *(const float4*)(A + (size_t)(m0 + r)*Kdim + k0 + cc4);
        As[cc4+0][r] = av.x; As[cc4+1][r] = av.y; As[cc4+2][r] = av.z; As[cc4+3][r] = av.w;
        *(float4*)(&Bs[r2][c2]) = *(const float4*)(Bw + (size_t)(k0 + r2)*256 + n0 + c2);
        __syncthreads();
#pragma unroll
        for (int k = 0; k < 8; k++) {
            float a[8], bb[8];
#pragma unroll
            for (int i = 0; i < 8; i++) a[i]  = As[k][ty*8 + i];
#pragma unroll
            for (int j = 0; j < 8; j++) bb[j] = Bs[k][tx*8 + j];
#pragma unroll
            for (int i = 0; i < 8; i++)
#pragma unroll
                for (int j = 0; j < 8; j++) acc[i][j] = fmaf(a[i], bb[j], acc[i][j]);
        }
        __syncthreads();
    }
#pragma unroll
    for (int i = 0; i < 8; i++) {
        size_t row = (size_t)m0 + ty*8 + i;
#pragma unroll
        for (int j = 0; j < 8; j++) {
            int colI = n0 + tx*8 + j;
            float v = acc[i][j] + bias[colI];
            C[row*256 + colI] = fmaxf(v, 0.f);
        }
    }
}

// -------------------- 7) segment max over fixed 33-edge groups -------------
__global__ void segmax_kernel() {
    int idx = blockIdx.x*blockDim.x + threadIdx.x;
    int g = idx >> 8, ch = idx & 255;
    float m = 0.f;
    const float* h2 = g_H2 + (size_t)g*KNBR*H2DIM + ch;
#pragma unroll
    for (int s = 0; s < KNBR; s++) m = fmaxf(m, h2[(size_t)s*H2DIM]);
    g_agg[(size_t)g*H2DIM + ch] = m;
}

// -------------------- launch ------------------------------------------------
extern "C" void kernel_launch(void* const* d_in, const int* in_sizes, int n_in,
                              void* d_out, int out_size) {
    const float* x     = (const float*)d_in[0];
    const float* pos   = (const float*)d_in[1];
    const int*   batch = (const int*)  d_in[2];
    const float* lw1   = (const float*)d_in[3];
    const float* lb1   = (const float*)d_in[4];
    const float* lw2   = (const float*)d_in[5];
    const float* lb2   = (const float*)d_in[6];
    const float* gw1   = (const float*)d_in[7];
    const float* gb1   = (const float*)d_in[8];
    float* dout = (float*)d_out;

    cudaFuncSetAttribute(fps_kernel, cudaFuncAttributeMaxDynamicSharedMemorySize,
                         3*NPTS*(int)sizeof(float));
    int bq_smem = 3*BQ_TILE*(int)sizeof(float) + 8*BQ_CAP*(int)sizeof(ull);
    cudaFuncSetAttribute(ballquery_kernel, cudaFuncAttributeMaxDynamicSharedMemorySize,
                         bq_smem);

    void *pH1 = nullptr, *pH2 = nullptr, *pAgg = nullptr;
    cudaGetSymbolAddress(&pH1,  g_H1);
    cudaGetSymbolAddress(&pH2,  g_H2);
    cudaGetSymbolAddress(&pAgg, g_agg);

    fps_kernel<<<NB, 512, 3*NPTS*sizeof(float)>>>(pos);
    gather_kernel<<<NCENT/256, 256>>>(pos, batch, dout);
    ballquery_kernel<<<NCENT/8, 256, bq_smem>>>(pos);
    pfeat_kernel<<<(NB*NPTS*H1DIM)/256, 256>>>(x, lw1, lb1);
    eh1_kernel<<<(NEDGE*H1DIM)/256, 256>>>(pos, lw1);
    sgemm_kernel<<<dim3(NEDGE/128, 2), 256>>>((const float*)pH1, lw2, lb2,
                                              (float*)pH2, H1DIM);
    segmax_kernel<<<(NCENT*H2DIM)/256, 256>>>();
    sgemm_kernel<<<dim3(NCENT/128, 2), 256>>>((const float*)pAgg, gw1, gb1,
                                              dout, H2DIM);
}

// round 4
// speedup vs baseline: 4.7027x; 4.7027x over previous
#include <cuda_runtime.h>
#include <cstdint>

#define NPTS   16384
#define NB     4
#define MPER   4096
#define NCENT  (NB*MPER)          // 16384 centroids
#define KNBR   33                 // K+1
#define NEDGE  (NCENT*KNBR)       // 540672 edges
#define H1DIM  128
#define H2DIM  256
#define CDIM   32
#define R2CONST 0.04f

#define OUT_POS_OFF   (NCENT*H2DIM)
#define OUT_BATCH_OFF (OUT_POS_OFF + NCENT*3)

typedef unsigned long long ull;

// -------------------- device scratch --------------------------------------
__device__ int   g_fps[NCENT];
__device__ int   g_gidx[NCENT];
__device__ float g_cent[NCENT*3];
__device__ int   g_nbr[NEDGE];
__device__ float g_mind  [NB*NPTS];                 // FPS min-dist (sorted slot order)
__device__ int   g_sortidx[NB*NPTS];                // sorted slot -> original idx
__device__ float g_A  [(size_t)NB*NPTS*H1DIM];
__device__ float g_H1 [(size_t)NEDGE*H1DIM];
__device__ float g_H2 [(size_t)NEDGE*H2DIM];
__device__ float g_agg[(size_t)NCENT*H2DIM];

// -------------------- 1) bucketed FPS, worklist-distributed updates --------
// Exact-equivalent FPS: 8^3 grid, per-cell packed max keys
// (d2bits:32 | invOrig:14 | slot:14), conservative fma-consistent AABB
// lower-bound pruning. Dirty-cell updates spread warp-per-cell/lane-per-point
// so no single owner thread serializes an iteration.
__device__ __forceinline__ int cellof(float x, float y, float z) {
    int ix = (int)(x * 8.0f); ix = ix < 0 ? 0 : (ix > 7 ? 7 : ix);
    int iy = (int)(y * 8.0f); iy = iy < 0 ? 0 : (iy > 7 ? 7 : iy);
    int iz = (int)(z * 8.0f); iz = iz < 0 ? 0 : (iz > 7 ? 7 : iz);
    return (iz << 6) | (iy << 3) | ix;
}

#define FPS_SMEM (3*NPTS*4 + 512*8 + 3*512*4)

__global__ void __launch_bounds__(512,1) fps_kernel(const float* __restrict__ pos) {
    int b = blockIdx.x;
    extern __shared__ float sm[];
    float* Xs = sm; float* Ys = sm + NPTS; float* Zs = sm + 2*NPTS;
    ull* cellkey = (ull*)(sm + 3*NPTS);          // 512 keys
    int* cs0  = (int*)(cellkey + 512);           // cell start
    int* cptr = cs0 + 512;                       // scatter ptr -> cell end
    int* wl   = cptr + 512;                      // dirty-cell worklist
    __shared__ ull   wred[16];
    __shared__ float qsh[3];
    __shared__ int   nd_sh;
    int tid = threadIdx.x, lane = tid & 31, wid = tid >> 5;
    const float* p = pos + (size_t)b*NPTS*3;
    float* gM = g_mind    + (size_t)b*NPTS;
    int*   gO = g_sortidx + (size_t)b*NPTS;

    cptr[tid] = 0;
    cellkey[tid] = 0ull;
    __syncthreads();

    // count points per cell
    for (int i = tid; i < NPTS; i += 512)
        atomicAdd(&cptr[cellof(p[3*i], p[3*i+1], p[3*i+2])], 1);
    __syncthreads();

    // exclusive prefix sum over 512 counts (warp 0) -> cs0
    if (wid == 0) {
        int carry = 0;
        for (int cc = 0; cc < 16; cc++) {
            int v0 = cptr[cc*32 + lane];
            int v = v0;
#pragma unroll
            for (int off = 1; off < 32; off <<= 1) {
                int o = __shfl_up_sync(0xffffffffu, v, off);
                if (lane >= off) v += o;
            }
            int tot = __shfl_sync(0xffffffffu, v, 31);
            cs0[cc*32 + lane] = v - v0 + carry;
            carry += tot;
        }
    }
    __syncthreads();
    cptr[tid] = cs0[tid];
    __syncthreads();

    // scatter into sorted order; init M (d2 vs point 0) and cell keys
    float q0x = p[0], q0y = p[1], q0z = p[2];
    for (int i = tid; i < NPTS; i += 512) {
        float x = p[3*i], y = p[3*i+1], z = p[3*i+2];
        int c = cellof(x, y, z);
        int s = atomicAdd(&cptr[c], 1);
        Xs[s] = x; Ys[s] = y; Zs[s] = z;
        gO[s] = i;
        float dx = x - q0x, dy = y - q0y, dz = z - q0z;
        float d2 = fmaf(dz, dz, fmaf(dy, dy, dx*dx));
        gM[s] = d2;
        ull key = ((ull)__float_as_uint(d2) << 32)
                | ((ull)(unsigned)(NPTS - 1 - i) << 14) | (unsigned)s;
        atomicMax(&cellkey[c], key);
    }
    if (tid == 0) g_fps[b*MPER] = 0;
    __syncthreads();

    const float CS = 0.125f;
    float lox = (float)(tid & 7) * CS;
    float loy = (float)((tid >> 3) & 7) * CS;
    float loz = (float)(tid >> 6) * CS;
    float hix = lox + CS, hiy = loy + CS, hiz = loz + CS;

    for (int t = 1; t < MPER; t++) {
        // ---- A: argmax over 512 cell keys ----
        ull mykey = cellkey[tid];
        ull key = mykey;
#pragma unroll
        for (int off = 16; off > 0; off >>= 1) {
            ull o2 = __shfl_down_sync(0xffffffffu, key, off);
            if (o2 > key) key = o2;
        }
        if (lane == 0) wred[wid] = key;
        if (tid == 0) nd_sh = 0;
        __syncthreads();
        if (wid == 0) {
            ull k2 = wred[lane & 15];
#pragma unroll
            for (int off = 8; off > 0; off >>= 1) {
                ull o2 = __shfl_down_sync(0xffffffffu, k2, off);
                if (o2 > k2) k2 = o2;
            }
            if (lane == 0) {
                int slot = (int)(k2 & 0x3FFFu);
                int orig = NPTS - 1 - (int)((k2 >> 14) & 0x3FFFu);
                g_fps[b*MPER + t] = orig;
                qsh[0] = Xs[slot]; qsh[1] = Ys[slot]; qsh[2] = Zs[slot];
            }
        }
        __syncthreads();
        float qx = qsh[0], qy = qsh[1], qz = qsh[2];

        // ---- B: dirty cells (AABB lower bound, fma-consistent) ----
        float cm = __uint_as_float((unsigned)(mykey >> 32));
        float lbx = fmaxf(fmaxf(lox - qx, qx - hix), 0.0f);
        float lby = fmaxf(fmaxf(loy - qy, qy - hiy), 0.0f);
        float lbz = fmaxf(fmaxf(loz - qz, qz - hiz), 0.0f);
        float lb2 = fmaf(lbz, lbz, fmaf(lby, lby, lbx*lbx));
        if (lb2 < cm) {
            cellkey[tid] = 0ull;
            wl[atomicAdd(&nd_sh, 1)] = tid;
        }
        __syncthreads();
        int nd = nd_sh;

        // ---- C: update dirty cells, warp-per-cell round robin ----
        for (int j = wid; j < nd; j += 16) {
            int c = wl[j];
            int s0 = cs0[c], s1 = cptr[c];
            ull best = 0ull;
            for (int s = s0 + lane; s < s1; s += 32) {
                float dx = Xs[s]-qx, dy = Ys[s]-qy, dz = Zs[s]-qz;
                float d2 = fmaf(dz, dz, fmaf(dy, dy, dx*dx));
                float m = gM[s];
                float nm = fminf(m, d2);
                if (nm < m) gM[s] = nm;
                int orig = gO[s];
                ull k = ((ull)__float_as_uint(nm) << 32)
                      | ((ull)(unsigned)(NPTS - 1 - orig) << 14) | (unsigned)s;
                if (k > best) best = k;
            }
#pragma unroll
            for (int off = 16; off > 0; off >>= 1) {
                ull o2 = __shfl_down_sync(0xffffffffu, best, off);
                if (o2 > best) best = o2;
            }
            if (lane == 0) atomicMax(&cellkey[c], best);
        }
        __syncthreads();
    }
}

// -------------------- 2) gather centroids + write pos/batch outputs --------
__global__ void gather_kernel(const float* __restrict__ pos,
                              const int* __restrict__ batch,
                              float* __restrict__ dout) {
    int i = blockIdx.x*blockDim.x + threadIdx.x;
    if (i >= NCENT) return;
    int b = i >> 12;
    int sel = g_fps[i];
    int g = b*NPTS + sel;
    float x = pos[3*g], y = pos[3*g+1], z = pos[3*g+2];
    g_cent[3*i] = x; g_cent[3*i+1] = y; g_cent[3*i+2] = z;
    g_gidx[i] = g;
    dout[OUT_POS_OFF + 3*i]   = x;
    dout[OUT_POS_OFF + 3*i+1] = y;
    dout[OUT_POS_OFF + 3*i+2] = z;
    dout[OUT_BATCH_OFF + i]   = (float)batch[g];
}

// -------------------- 3) ball query: 33 nearest within r -------------------
#define BQ_TILE 2048
#define BQ_CAP  1024
__global__ void __launch_bounds__(256,1) ballquery_kernel(const float* __restrict__ pos) {
    extern __shared__ float sm[];
    float* Xs = sm; float* Ys = sm + BQ_TILE; float* Zs = sm + 2*BQ_TILE;
    ull* buf = (ull*)(sm + 3*BQ_TILE);
    int tid = threadIdx.x;
    int wid = tid >> 5, lane = tid & 31;
    int c = blockIdx.x*8 + wid;
    int cloud = c >> 12;
    const float* pcloud = pos + (size_t)cloud*NPTS*3;
    float cx = g_cent[3*c], cy = g_cent[3*c+1], cz = g_cent[3*c+2];
    ull* mybuf = buf + (size_t)wid*BQ_CAP;
    int cnt = 0;
    for (int tile = 0; tile < NPTS/BQ_TILE; ++tile) {
        for (int i = tid; i < BQ_TILE; i += 256) {
            int pidx = tile*BQ_TILE + i;
            Xs[i] = pcloud[3*pidx]; Ys[i] = pcloud[3*pidx+1]; Zs[i] = pcloud[3*pidx+2];
        }
        __syncthreads();
        for (int i = lane; i < BQ_TILE; i += 32) {
            float dx = Xs[i]-cx, dy = Ys[i]-cy, dz = Zs[i]-cz;
            float d2 = fmaf(dz,dz,fmaf(dy,dy,dx*dx));
            bool hit = (d2 <= R2CONST);
            unsigned m = __ballot_sync(0xffffffffu, hit);
            int pre = __popc(m & ((1u << lane) - 1u));
            if (hit) {
                int slot = cnt + pre;
                if (slot < BQ_CAP)
                    mybuf[slot] = ((ull)__float_as_uint(d2) << 32)
                                | (unsigned)(tile*BQ_TILE + i);
            }
            cnt += __popc(m);
        }
        __syncthreads();
    }
    if (cnt > BQ_CAP) cnt = BQ_CAP;
    int selfg = g_gidx[c];
    for (int it = 0; it < KNBR; ++it) {
        ull mn = ~0ull;
        for (int j = lane; j < cnt; j += 32) {
            ull v = mybuf[j];
            if (v < mn) mn = v;
        }
#pragma unroll
        for (int off = 16; off > 0; off >>= 1) {
            ull o = __shfl_down_sync(0xffffffffu, mn, off);
            if (o < mn) mn = o;
        }
        mn = __shfl_sync(0xffffffffu, mn, 0);
        int nbr;
        if (mn == ~0ull) {
            nbr = selfg;
        } else {
            nbr = cloud*NPTS + (int)(mn & 0xffffffffu);
            for (int j = lane; j < cnt; j += 32)
                if (mybuf[j] == mn) mybuf[j] = ~0ull;
        }
        if (lane == 0) g_nbr[c*KNBR + it] = nbr;
    }
}

// -------------------- 4) per-point layer-1 x-part --------------------------
__global__ void pfeat_kernel(const float* __restrict__ x,
                             const float* __restrict__ lw1,
                             const float* __restrict__ lb1) {
    int idx = blockIdx.x*blockDim.x + threadIdx.x;
    int p = idx >> 7, ch = idx & 127;
    float acc = lb1[ch];
    const float* xp = x + (size_t)p*CDIM;
#pragma unroll
    for (int j = 0; j < CDIM; j++)
        acc = fmaf(xp[j], lw1[j*H1DIM + ch], acc);
    g_A[(size_t)p*H1DIM + ch] = acc;
}

// -------------------- 5) per-edge layer-1 ----------------------------------
__global__ void eh1_kernel(const float* __restrict__ pos,
                           const float* __restrict__ lw1) {
    int idx = blockIdx.x*blockDim.x + threadIdx.x;
    int e = idx >> 7, k = idx & 127;
    int c = e / KNBR;
    int col = g_nbr[e];
    float dx = pos[3*col]   - g_cent[3*c];
    float dy = pos[3*col+1] - g_cent[3*c+1];
    float dz = pos[3*col+2] - g_cent[3*c+2];
    float h = g_A[(size_t)col*H1DIM + k];
    h = fmaf(dx, lw1[32*H1DIM + k], h);
    h = fmaf(dy, lw1[33*H1DIM + k], h);
    h = fmaf(dz, lw1[34*H1DIM + k], h);
    g_H1[(size_t)e*H1DIM + k] = fmaxf(h, 0.0f);
}

// -------------------- 6) tiled SGEMM, C = relu(A@B + bias) -----------------
__global__ void __launch_bounds__(256) sgemm_kernel(const float* __restrict__ A,
                                                    const float* __restrict__ Bw,
                                                    const float* __restrict__ bias,
                                                    float* __restrict__ C,
                                                    int Kdim) {
    __shared__ float As[8][128];
    __shared__ float Bs[8][128];
    int t = threadIdx.x;
    int tx = t & 15, ty = t >> 4;
    int m0 = blockIdx.x * 128, n0 = blockIdx.y * 128;
    float acc[8][8];
#pragma unroll
    for (int i = 0; i < 8; i++)
#pragma unroll
        for (int j = 0; j < 8; j++) acc[i][j] = 0.f;
    int r  = t >> 1, cc4 = (t & 1) * 4;
    int r2 = t >> 5, c2  = (t & 31) * 4;
    for (int k0 = 0; k0 < Kdim; k0 += 8) {
        float4 av = *(const float4*)(A + (size_t)(m0 + r)*Kdim + k0 + cc4);
        As[cc4+0][r] = av.x; As[cc4+1][r] = av.y; As[cc4+2][r] = av.z; As[cc4+3][r] = av.w;
        *(float4*)(&Bs[r2][c2]) = *(const float4*)(Bw + (size_t)(k0 + r2)*256 + n0 + c2);
        __syncthreads();
#pragma unroll
        for (int k = 0; k < 8; k++) {
            float a[8], bb[8];
#pragma unroll
            for (int i = 0; i < 8; i++) a[i]  = As[k][ty*8 + i];
#pragma unroll
            for (int j = 0; j < 8; j++) bb[j] = Bs[k][tx*8 + j];
#pragma unroll
            for (int i = 0; i < 8; i++)
#pragma unroll
                for (int j = 0; j < 8; j++) acc[i][j] = fmaf(a[i], bb[j], acc[i][j]);
        }
        __syncthreads();
    }
#pragma unroll
    for (int i = 0; i < 8; i++) {
        size_t row = (size_t)m0 + ty*8 + i;
#pragma unroll
        for (int j = 0; j < 8; j++) {
            int colI = n0 + tx*8 + j;
            float v = acc[i][j] + bias[colI];
            C[row*256 + colI] = fmaxf(v, 0.f);
        }
    }
}

// -------------------- 7) segment max over fixed 33-edge groups -------------
__global__ void segmax_kernel() {
    int idx = blockIdx.x*blockDim.x + threadIdx.x;
    int g = idx >> 8, ch = idx & 255;
    float m = 0.f;
    const float* h2 = g_H2 + (size_t)g*KNBR*H2DIM + ch;
#pragma unroll
    for (int s = 0; s < KNBR; s++) m = fmaxf(m, h2[(size_t)s*H2DIM]);
    g_agg[(size_t)g*H2DIM + ch] = m;
}

// -------------------- launch ------------------------------------------------
extern "C" void kernel_launch(void* const* d_in, const int* in_sizes, int n_in,
                              void* d_out, int out_size) {
    const float* x     = (const float*)d_in[0];
    const float* pos   = (const float*)d_in[1];
    const int*   batch = (const int*)  d_in[2];
    const float* lw1   = (const float*)d_in[3];
    const float* lb1   = (const float*)d_in[4];
    const float* lw2   = (const float*)d_in[5];
    const float* lb2   = (const float*)d_in[6];
    const float* gw1   = (const float*)d_in[7];
    const float* gb1   = (const float*)d_in[8];
    float* dout = (float*)d_out;

    cudaFuncSetAttribute(fps_kernel, cudaFuncAttributeMaxDynamicSharedMemorySize,
                         FPS_SMEM);
    int bq_smem = 3*BQ_TILE*(int)sizeof(float) + 8*BQ_CAP*(int)sizeof(ull);
    cudaFuncSetAttribute(ballquery_kernel, cudaFuncAttributeMaxDynamicSharedMemorySize,
                         bq_smem);

    void *pH1 = nullptr, *pH2 = nullptr, *pAgg = nullptr;
    cudaGetSymbolAddress(&pH1,  g_H1);
    cudaGetSymbolAddress(&pH2,  g_H2);
    cudaGetSymbolAddress(&pAgg, g_agg);

    fps_kernel<<<NB, 512, FPS_SMEM>>>(pos);
    gather_kernel<<<NCENT/256, 256>>>(pos, batch, dout);
    ballquery_kernel<<<NCENT/8, 256, bq_smem>>>(pos);
    pfeat_kernel<<<(NB*NPTS*H1DIM)/256, 256>>>(x, lw1, lb1);
    eh1_kernel<<<(NEDGE*H1DIM)/256, 256>>>(pos, lw1);
    sgemm_kernel<<<dim3(NEDGE/128, 2), 256>>>((const float*)pH1, lw2, lb2,
                                              (float*)pH2, H1DIM);
    segmax_kernel<<<(NCENT*H2DIM)/256, 256>>>();
    sgemm_kernel<<<dim3(NCENT/128, 2), 256>>>((const float*)pAgg, gw1, gb1,
                                              dout, H2DIM);
}

// round 5
// speedup vs baseline: 5.4123x; 1.1509x over previous
#include <cuda_runtime.h>
#include <cstdint>

#define NPTS   16384
#define NB     4
#define MPER   4096
#define NCENT  (NB*MPER)          // 16384 centroids
#define KNBR   33                 // K+1
#define NEDGE  (NCENT*KNBR)       // 540672 edges
#define H1DIM  128
#define H2DIM  256
#define CDIM   32
#define R2CONST 0.04f

#define OUT_POS_OFF   (NCENT*H2DIM)
#define OUT_BATCH_OFF (OUT_POS_OFF + NCENT*3)

typedef unsigned long long ull;

// -------------------- device scratch --------------------------------------
__device__ int   g_fps[NCENT];
__device__ int   g_gidx[NCENT];
__device__ float g_cent[NCENT*3];
__device__ int   g_nbr[NEDGE];
__device__ ull   g_K[NB*NPTS];                      // packed (d2|invorig|slot)
__device__ float g_A  [(size_t)NB*NPTS*H1DIM];
__device__ float g_H1 [(size_t)NEDGE*H1DIM];
__device__ float g_H2 [(size_t)NEDGE*H2DIM];
__device__ float g_agg[(size_t)NCENT*H2DIM];

// -------------------- 1) bucketed FPS -------------------------------------
// Exact-equivalent FPS: 8^3 grid, per-cell packed max keys
// (d2bits:32 | invOrig:14 | slot:14), conservative fma-consistent AABB
// pruning, worklist-distributed updates, hierarchical incremental argmax.
__device__ __forceinline__ int cellof(float x, float y, float z) {
    int ix = (int)(x * 8.0f); ix = ix < 0 ? 0 : (ix > 7 ? 7 : ix);
    int iy = (int)(y * 8.0f); iy = iy < 0 ? 0 : (iy > 7 ? 7 : iy);
    int iz = (int)(z * 8.0f); iz = iz < 0 ? 0 : (iz > 7 ? 7 : iz);
    return (iz << 6) | (iy << 3) | ix;
}

#define FPS_SMEM (3*NPTS*4 + 512*8 + 3*512*4)

__global__ void __launch_bounds__(512,1) fps_kernel(const float* __restrict__ pos) {
    int b = blockIdx.x;
    extern __shared__ float sm[];
    float* Xs = sm; float* Ys = sm + NPTS; float* Zs = sm + 2*NPTS;
    ull* cellkey = (ull*)(sm + 3*NPTS);          // 512 keys
    int* cs0  = (int*)(cellkey + 512);           // cell start
    int* cptr = cs0 + 512;                       // cell end
    int* wl   = cptr + 512;                      // dirty-cell worklist
    __shared__ ull   warpmax[16];
    __shared__ int   warplist[16];
    __shared__ float qsh[3];
    __shared__ int   nd_sh, nw_sh;
    int tid = threadIdx.x, lane = tid & 31, wid = tid >> 5;
    const float* p = pos + (size_t)b*NPTS*3;
    ull* gK = g_K + (size_t)b*NPTS;

    cptr[tid] = 0;
    cellkey[tid] = 0ull;
    __syncthreads();

    // count points per cell
    for (int i = tid; i < NPTS; i += 512)
        atomicAdd(&cptr[cellof(p[3*i], p[3*i+1], p[3*i+2])], 1);
    __syncthreads();

    // exclusive prefix sum over 512 counts (warp 0) -> cs0
    if (wid == 0) {
        int carry = 0;
        for (int cc = 0; cc < 16; cc++) {
            int v0 = cptr[cc*32 + lane];
            int v = v0;
#pragma unroll
            for (int off = 1; off < 32; off <<= 1) {
                int o = __shfl_up_sync(0xffffffffu, v, off);
                if (lane >= off) v += o;
            }
            int tot = __shfl_sync(0xffffffffu, v, 31);
            cs0[cc*32 + lane] = v - v0 + carry;
            carry += tot;
        }
    }
    __syncthreads();
    cptr[tid] = cs0[tid];
    __syncthreads();

    // scatter into sorted order; init packed keys (d2 vs point 0)
    float q0x = p[0], q0y = p[1], q0z = p[2];
    for (int i = tid; i < NPTS; i += 512) {
        float x = p[3*i], y = p[3*i+1], z = p[3*i+2];
        int c = cellof(x, y, z);
        int s = atomicAdd(&cptr[c], 1);
        Xs[s] = x; Ys[s] = y; Zs[s] = z;
        float dx = x - q0x, dy = y - q0y, dz = z - q0z;
        float d2 = fmaf(dz, dz, fmaf(dy, dy, dx*dx));
        ull key = ((ull)__float_as_uint(d2) << 32)
                | ((ull)(unsigned)(NPTS - 1 - i) << 14) | (unsigned)s;
        gK[s] = key;
        atomicMax(&cellkey[c], key);
    }
    if (tid == 0) g_fps[b*MPER] = 0;
    __syncthreads();

    // initial warpmax
    {
        ull key = cellkey[tid];
#pragma unroll
        for (int off = 16; off > 0; off >>= 1) {
            ull o2 = __shfl_down_sync(0xffffffffu, key, off);
            if (o2 > key) key = o2;
        }
        if (lane == 0) warpmax[wid] = key;
    }
    __syncthreads();

    const float CS = 0.125f;
    float lox = (float)(tid & 7) * CS;
    float loy = (float)((tid >> 3) & 7) * CS;
    float loz = (float)(tid >> 6) * CS;
    float hix = lox + CS, hiy = loy + CS, hiz = loz + CS;

    for (int t = 1; t < MPER; t++) {
        // ---- A: argmax over 16 warp maxima (warp 0 only) ----
        if (wid == 0) {
            ull k2 = warpmax[lane & 15];
#pragma unroll
            for (int off = 8; off > 0; off >>= 1) {
                ull o2 = __shfl_down_sync(0xffffffffu, k2, off);
                if (o2 > k2) k2 = o2;
            }
            if (lane == 0) {
                int slot = (int)(k2 & 0x3FFFu);
                int orig = NPTS - 1 - (int)((k2 >> 14) & 0x3FFFu);
                g_fps[b*MPER + t] = orig;
                qsh[0] = Xs[slot]; qsh[1] = Ys[slot]; qsh[2] = Zs[slot];
                nd_sh = 0; nw_sh = 0;
            }
        }
        __syncthreads();
        float qx = qsh[0], qy = qsh[1], qz = qsh[2];

        // ---- B: dirty cells (AABB lower bound, fma-consistent) ----
        ull mykey = cellkey[tid];
        float cm = __uint_as_float((unsigned)(mykey >> 32));
        float lbx = fmaxf(fmaxf(lox - qx, qx - hix), 0.0f);
        float lby = fmaxf(fmaxf(loy - qy, qy - hiy), 0.0f);
        float lbz = fmaxf(fmaxf(loz - qz, qz - hiz), 0.0f);
        float lb2 = fmaf(lbz, lbz, fmaf(lby, lby, lbx*lbx));
        bool d = (lb2 < cm);
        if (d) wl[atomicAdd(&nd_sh, 1)] = tid;
        unsigned m = __ballot_sync(0xffffffffu, d);
        if (lane == 0 && m) warplist[atomicAdd(&nw_sh, 1)] = wid;
        __syncthreads();
        int nd = nd_sh, nw = nw_sh;

        // ---- C: update dirty cells, warp-per-cell (unique -> plain store) --
        for (int j = wid; j < nd; j += 16) {
            int c = wl[j];
            int s0 = cs0[c], s1 = cptr[c];
            ull best = 0ull;
            for (int s = s0 + lane; s < s1; s += 32) {
                ull k = gK[s];
                float dx = Xs[s]-qx, dy = Ys[s]-qy, dz = Zs[s]-qz;
                float d2 = fmaf(dz, dz, fmaf(dy, dy, dx*dx));
                float om = __uint_as_float((unsigned)(k >> 32));
                float nm = fminf(om, d2);
                if (nm < om) {
                    k = ((ull)__float_as_uint(nm) << 32) | (k & 0xFFFFFFFFull);
                    gK[s] = k;
                }
                if (k > best) best = k;
            }
#pragma unroll
            for (int off = 16; off > 0; off >>= 1) {
                ull o2 = __shfl_down_sync(0xffffffffu, best, off);
                if (o2 > best) best = o2;
            }
            if (lane == 0) cellkey[c] = best;
        }
        __syncthreads();

        // ---- D: recompute warpmax for warps containing dirty cells --------
        for (int j = wid; j < nw; j += 16) {
            int w = warplist[j];
            ull key = cellkey[(w << 5) + lane];
#pragma unroll
            for (int off = 16; off > 0; off >>= 1) {
                ull o2 = __shfl_down_sync(0xffffffffu, key, off);
                if (o2 > key) key = o2;
            }
            if (lane == 0) warpmax[w] = key;
        }
        __syncthreads();
    }
}

// -------------------- 2) gather centroids + write pos/batch outputs --------
__global__ void gather_kernel(const float* __restrict__ pos,
                              const int* __restrict__ batch,
                              float* __restrict__ dout) {
    int i = blockIdx.x*blockDim.x + threadIdx.x;
    if (i >= NCENT) return;
    int b = i >> 12;
    int sel = g_fps[i];
    int g = b*NPTS + sel;
    float x = pos[3*g], y = pos[3*g+1], z = pos[3*g+2];
    g_cent[3*i] = x; g_cent[3*i+1] = y; g_cent[3*i+2] = z;
    g_gidx[i] = g;
    dout[OUT_POS_OFF + 3*i]   = x;
    dout[OUT_POS_OFF + 3*i+1] = y;
    dout[OUT_POS_OFF + 3*i+2] = z;
    dout[OUT_BATCH_OFF + i]   = (float)batch[g];
}

// -------------------- 3) ball query: 33 nearest within r -------------------
#define BQ_TILE 2048
#define BQ_CAP  1024
__global__ void __launch_bounds__(256,1) ballquery_kernel(const float* __restrict__ pos) {
    extern __shared__ float sm[];
    float* Xs = sm; float* Ys = sm + BQ_TILE; float* Zs = sm + 2*BQ_TILE;
    ull* buf = (ull*)(sm + 3*BQ_TILE);
    int tid = threadIdx.x;
    int wid = tid >> 5, lane = tid & 31;
    int c = blockIdx.x*8 + wid;
    int cloud = c >> 12;
    const float* pcloud = pos + (size_t)cloud*NPTS*3;
    float cx = g_cent[3*c], cy = g_cent[3*c+1], cz = g_cent[3*c+2];
    ull* mybuf = buf + (size_t)wid*BQ_CAP;
    int cnt = 0;
    for (int tile = 0; tile < NPTS/BQ_TILE; ++tile) {
        for (int i = tid; i < BQ_TILE; i += 256) {
            int pidx = tile*BQ_TILE + i;
            Xs[i] = pcloud[3*pidx]; Ys[i] = pcloud[3*pidx+1]; Zs[i] = pcloud[3*pidx+2];
        }
        __syncthreads();
        for (int i = lane; i < BQ_TILE; i += 32) {
            float dx = Xs[i]-cx, dy = Ys[i]-cy, dz = Zs[i]-cz;
            float d2 = fmaf(dz,dz,fmaf(dy,dy,dx*dx));
            bool hit = (d2 <= R2CONST);
            unsigned m = __ballot_sync(0xffffffffu, hit);
            int pre = __popc(m & ((1u << lane) - 1u));
            if (hit) {
                int slot = cnt + pre;
                if (slot < BQ_CAP)
                    mybuf[slot] = ((ull)__float_as_uint(d2) << 32)
                                | (unsigned)(tile*BQ_TILE + i);
            }
            cnt += __popc(m);
        }
        __syncthreads();
    }
    if (cnt > BQ_CAP) cnt = BQ_CAP;
    int selfg = g_gidx[c];
    for (int it = 0; it < KNBR; ++it) {
        ull mn = ~0ull;
        for (int j = lane; j < cnt; j += 32) {
            ull v = mybuf[j];
            if (v < mn) mn = v;
        }
#pragma unroll
        for (int off = 16; off > 0; off >>= 1) {
            ull o = __shfl_down_sync(0xffffffffu, mn, off);
            if (o < mn) mn = o;
        }
        mn = __shfl_sync(0xffffffffu, mn, 0);
        int nbr;
        if (mn == ~0ull) {
            nbr = selfg;
        } else {
            nbr = cloud*NPTS + (int)(mn & 0xffffffffu);
            for (int j = lane; j < cnt; j += 32)
                if (mybuf[j] == mn) mybuf[j] = ~0ull;
        }
        if (lane == 0) g_nbr[c*KNBR + it] = nbr;
    }
}

// -------------------- 4) per-point layer-1 x-part --------------------------
__global__ void pfeat_kernel(const float* __restrict__ x,
                             const float* __restrict__ lw1,
                             const float* __restrict__ lb1) {
    int idx = blockIdx.x*blockDim.x + threadIdx.x;
    int p = idx >> 7, ch = idx & 127;
    float acc = lb1[ch];
    const float* xp = x + (size_t)p*CDIM;
#pragma unroll
    for (int j = 0; j < CDIM; j++)
        acc = fmaf(xp[j], lw1[j*H1DIM + ch], acc);
    g_A[(size_t)p*H1DIM + ch] = acc;
}

// -------------------- 5) per-edge layer-1 (warp per edge, float4) ----------
__global__ void eh1_kernel(const float* __restrict__ pos,
                           const float* __restrict__ lw1) {
    int idx = blockIdx.x*blockDim.x + threadIdx.x;   // NEDGE*32
    int e = idx >> 5, k4 = (idx & 31) * 4;
    int c = e / KNBR;
    int col = g_nbr[e];
    float dx = pos[3*col]   - g_cent[3*c];
    float dy = pos[3*col+1] - g_cent[3*c+1];
    float dz = pos[3*col+2] - g_cent[3*c+2];
    float4 a  = *(const float4*)(g_A + (size_t)col*H1DIM + k4);
    float4 wx = *(const float4*)(lw1 + 32*H1DIM + k4);
    float4 wy = *(const float4*)(lw1 + 33*H1DIM + k4);
    float4 wz = *(const float4*)(lw1 + 34*H1DIM + k4);
    float4 h;
    h.x = fmaxf(fmaf(dz, wz.x, fmaf(dy, wy.x, fmaf(dx, wx.x, a.x))), 0.f);
    h.y = fmaxf(fmaf(dz, wz.y, fmaf(dy, wy.y, fmaf(dx, wx.y, a.y))), 0.f);
    h.z = fmaxf(fmaf(dz, wz.z, fmaf(dy, wy.z, fmaf(dx, wx.z, a.z))), 0.f);
    h.w = fmaxf(fmaf(dz, wz.w, fmaf(dy, wy.w, fmaf(dx, wx.w, a.w))), 0.f);
    *(float4*)(g_H1 + (size_t)e*H1DIM + k4) = h;
}

// -------------------- 6) tiled SGEMM, C = relu(A@B + bias) -----------------
__global__ void __launch_bounds__(256) sgemm_kernel(const float* __restrict__ A,
                                                    const float* __restrict__ Bw,
                                                    const float* __restrict__ bias,
                                                    float* __restrict__ C,
                                                    int Kdim) {
    __shared__ float As[8][128];
    __shared__ float Bs[8][128];
    int t = threadIdx.x;
    int tx = t & 15, ty = t >> 4;
    int m0 = blockIdx.x * 128, n0 = blockIdx.y * 128;
    float acc[8][8];
#pragma unroll
    for (int i = 0; i < 8; i++)
#pragma unroll
        for (int j = 0; j < 8; j++) acc[i][j] = 0.f;
    int r  = t >> 1, cc4 = (t & 1) * 4;
    int r2 = t >> 5, c2  = (t & 31) * 4;
    for (int k0 = 0; k0 < Kdim; k0 += 8) {
        float4 av = *(const float4*)(A + (size_t)(m0 + r)*Kdim + k0 + cc4);
        As[cc4+0][r] = av.x; As[cc4+1][r] = av.y; As[cc4+2][r] = av.z; As[cc4+3][r] = av.w;
        *(float4*)(&Bs[r2][c2]) = *(const float4*)(Bw + (size_t)(k0 + r2)*256 + n0 + c2);
        __syncthreads();
#pragma unroll
        for (int k = 0; k < 8; k++) {
            float4 a0 = *(const float4*)(&As[k][ty*8]);
            float4 a1 = *(const float4*)(&As[k][ty*8+4]);
            float4 b0 = *(const float4*)(&Bs[k][tx*8]);
            float4 b1 = *(const float4*)(&Bs[k][tx*8+4]);
            float a[8] = {a0.x,a0.y,a0.z,a0.w,a1.x,a1.y,a1.z,a1.w};
            float bb[8] = {b0.x,b0.y,b0.z,b0.w,b1.x,b1.y,b1.z,b1.w};
#pragma unroll
            for (int i = 0; i < 8; i++)
#pragma unroll
                for (int j = 0; j < 8; j++) acc[i][j] = fmaf(a[i], bb[j], acc[i][j]);
        }
        __syncthreads();
    }
#pragma unroll
    for (int i = 0; i < 8; i++) {
        size_t row = (size_t)m0 + ty*8 + i;
#pragma unroll
        for (int j = 0; j < 8; j++) {
            int colI = n0 + tx*8 + j;
            float v = acc[i][j] + bias[colI];
            C[row*256 + colI] = fmaxf(v, 0.f);
        }
    }
}

// -------------------- 7) segment max over fixed 33-edge groups (float4) ----
__global__ void segmax_kernel() {
    int idx = blockIdx.x*blockDim.x + threadIdx.x;   // NCENT*64
    int g = idx >> 6, ch4 = (idx & 63) * 4;
    float4 m = make_float4(0.f, 0.f, 0.f, 0.f);
    const float* h2 = g_H2 + (size_t)g*KNBR*H2DIM + ch4;
#pragma unroll
    for (int s = 0; s < KNBR; s++) {
        float4 v = *(const float4*)(h2 + (size_t)s*H2DIM);
        m.x = fmaxf(m.x, v.x); m.y = fmaxf(m.y, v.y);
        m.z = fmaxf(m.z, v.z); m.w = fmaxf(m.w, v.w);
    }
    *(float4*)(g_agg + (size_t)g*H2DIM + ch4) = m;
}

// -------------------- launch ------------------------------------------------
extern "C" void kernel_launch(void* const* d_in, const int* in_sizes, int n_in,
                              void* d_out, int out_size) {
    const float* x     = (const float*)d_in[0];
    const float* pos   = (const float*)d_in[1];
    const int*   batch = (const int*)  d_in[2];
    const float* lw1   = (const float*)d_in[3];
    const float* lb1   = (const float*)d_in[4];
    const float* lw2   = (const float*)d_in[5];
    const float* lb2   = (const float*)d_in[6];
    const float* gw1   = (const float*)d_in[7];
    const float* gb1   = (const float*)d_in[8];
    float* dout = (float*)d_out;

    cudaFuncSetAttribute(fps_kernel, cudaFuncAttributeMaxDynamicSharedMemorySize,
                         FPS_SMEM);
    int bq_smem = 3*BQ_TILE*(int)sizeof(float) + 8*BQ_CAP*(int)sizeof(ull);
    cudaFuncSetAttribute(ballquery_kernel, cudaFuncAttributeMaxDynamicSharedMemorySize,
                         bq_smem);

    void *pH1 = nullptr, *pH2 = nullptr, *pAgg = nullptr;
    cudaGetSymbolAddress(&pH1,  g_H1);
    cudaGetSymbolAddress(&pH2,  g_H2);
    cudaGetSymbolAddress(&pAgg, g_agg);

    fps_kernel<<<NB, 512, FPS_SMEM>>>(pos);
    gather_kernel<<<NCENT/256, 256>>>(pos, batch, dout);
    ballquery_kernel<<<NCENT/8, 256, bq_smem>>>(pos);
    pfeat_kernel<<<(NB*NPTS*H1DIM)/256, 256>>>(x, lw1, lb1);
    eh1_kernel<<<(NEDGE*32)/256, 256>>>(pos, lw1);
    sgemm_kernel<<<dim3(NEDGE/128, 2), 256>>>((const float*)pH1, lw2, lb2,
                                              (float*)pH2, H1DIM);
    segmax_kernel<<<(NCENT*64)/256, 256>>>();
    sgemm_kernel<<<dim3(NCENT/128, 2), 256>>>((const float*)pAgg, gw1, gb1,
                                              dout, H2DIM);
}